// round 9
// baseline (speedup 1.0000x reference)
#include <cuda_runtime.h>
#include <math.h>

#define NN   100000
#define EE   1600000
#define DD   128
#define GG   128
#define LL   4
#define NCLS 10
#define EPSV 1e-5f
#define NB   391          // ceil(NN/256) scan blocks

// ---------------- scratch (static device globals; no allocation) ----------------
static __device__ __align__(16) float g_h [(size_t)NN * DD];   // GEMM output (gather source)
static __device__ __align__(16) float g_h2[(size_t)NN * DD];   // SpMM output
static __device__ __align__(16) float g_am[GG * DD];           // alpha * mean
static __device__ __align__(16) float g_wr[GG * DD];           // gn_weight * rstd
static __device__ __align__(16) float g_pool[GG * DD];         // pooled sums
static __device__ __align__(16) float g_dis[NN];
static __device__ __align__(8)  int2  g_edge[EE];              // {col, weight-as-int}
static __device__ int   g_batch[NN];
static __device__ int   g_cnt[NN];
static __device__ int   g_fill[NN];
static __device__ int   g_rowptr[NN + 1];
static __device__ int   g_gptr[GG + 1];
static __device__ int   g_part[NB];
static __device__ int   g_i64;

union F4U64 { float4 f; unsigned long long u[2]; float s[4]; };

// ---------------- dtype detection: int64 vs int32 index buffers ----------------
__global__ void k_detect(const int* __restrict__ eiw) {
    __shared__ int bad;
    if (threadIdx.x == 0) bad = 0;
    __syncthreads();
    // If int64 (little-endian, values in [0,1e5)), every odd 32-bit word is 0.
    for (int i = threadIdx.x; i < 2048; i += blockDim.x)
        if (eiw[2 * i + 1] != 0) bad = 1;
    __syncthreads();
    if (threadIdx.x == 0) g_i64 = bad ? 0 : 1;
}

// ---------------- preprocessing ----------------
__global__ void k_init() {
    int i = blockIdx.x * blockDim.x + threadIdx.x;
    int stride = gridDim.x * blockDim.x;
    for (int n = i; n < NN; n += stride) { g_cnt[n] = 0; g_fill[n] = 0; }
}

__global__ void k_hist(const void* __restrict__ ei) {
    int e = blockIdx.x * blockDim.x + threadIdx.x;
    if (e >= EE) return;
    int d = g_i64 ? (int)((const long long*)ei)[EE + e] : ((const int*)ei)[EE + e];
    if ((unsigned)d >= NN) d = 0;
    atomicAdd(&g_cnt[d], 1);
}

// batch is sorted: derive g_gptr from boundaries, no atomics.
__global__ void k_cvt_batch(const void* __restrict__ batch) {
    int n = blockIdx.x * blockDim.x + threadIdx.x;
    if (n >= NN) return;
    int b, bp = -1;
    if (g_i64) {
        const long long* p = (const long long*)batch;
        b = (int)p[n];
        if (n > 0) bp = (int)p[n - 1];
    } else {
        const int* p = (const int*)batch;
        b = p[n];
        if (n > 0) bp = p[n - 1];
    }
    if ((unsigned)b >= GG) b = 0;
    if (n > 0 && (unsigned)bp >= GG) bp = 0;
    g_batch[n] = b;
    if (b != bp)
        for (int g = bp + 1; g <= b; g++) g_gptr[g] = n;
    if (n == NN - 1)
        for (int g = b + 1; g <= GG; g++) g_gptr[g] = NN;
}

// ---------------- parallel 3-step scan (also computes dis = rsqrt(deg)) -----------
__global__ void k_scan1() {
    __shared__ int sh[256];
    int b = blockIdx.x, t = threadIdx.x;
    int i = b * 256 + t;
    int v = (i < NN) ? g_cnt[i] : 0;
    if (i < NN) g_dis[i] = rsqrtf((float)(v + 1));
    sh[t] = v;
    __syncthreads();
    for (int o = 128; o > 0; o >>= 1) {
        if (t < o) sh[t] += sh[t + o];
        __syncthreads();
    }
    if (t == 0) g_part[b] = sh[0];
}
__global__ void k_scan2() {
    if (threadIdx.x == 0) {
        int r = 0;
        for (int i = 0; i < NB; i++) { int v = g_part[i]; g_part[i] = r; r += v; }
        g_rowptr[NN] = EE;
    }
}
__global__ void k_scan3() {
    __shared__ int sh[256];
    int b = blockIdx.x, t = threadIdx.x;
    int i = b * 256 + t;
    int v = (i < NN) ? g_cnt[i] : 0;
    sh[t] = v;
    __syncthreads();
    for (int o = 1; o < 256; o <<= 1) {
        int x = (t >= o) ? sh[t - o] : 0;
        __syncthreads();
        sh[t] += x;
        __syncthreads();
    }
    if (i < NN) g_rowptr[i] = g_part[b] + sh[t] - v;
}

__global__ void k_scatter(const void* __restrict__ ei) {
    int e = blockIdx.x * blockDim.x + threadIdx.x;
    if (e >= EE) return;
    int s, d;
    if (g_i64) {
        const long long* p = (const long long*)ei;
        s = (int)p[e]; d = (int)p[EE + e];
    } else {
        const int* p = (const int*)ei;
        s = p[e]; d = p[EE + e];
    }
    if ((unsigned)s >= NN) s = 0;
    if ((unsigned)d >= NN) d = 0;
    int pos = g_rowptr[d] + atomicAdd(&g_fill[d], 1);
    g_edge[pos] = make_int2(s, __float_as_int(g_dis[s] * g_dis[d]));
}

// ---------------- GEMM core (shared by plain and fused variants) ----------------
// 256 threads/block; 64 rows x 128 cols per block; X tile transposed in smem,
// W staged in 16-wide k chunks. 16 FFMA2 per k-step per thread.
__device__ __forceinline__ void gemm_core(float xsT[128][68], float ws[16][128],
                                          const float* __restrict__ W,
                                          int row0, int tid) {
    int tm = tid & 15, tn = tid >> 4;
    unsigned long long acc2[4][4];
    #pragma unroll
    for (int i = 0; i < 4; i++)
        #pragma unroll
        for (int j = 0; j < 4; j++) acc2[i][j] = 0ull;

    const float4* W4 = (const float4*)W;
    for (int kc = 0; kc < 8; kc++) {
        __syncthreads();
        float4* ws4 = (float4*)&ws[0][0];
        #pragma unroll
        for (int i = 0; i < 2; i++) ws4[tid + i * 256] = W4[kc * 512 + tid + i * 256];
        __syncthreads();
        #pragma unroll
        for (int k = 0; k < 16; k++) {
            int kk = kc * 16 + k;
            F4U64 av, b0, b1;
            av.f = *(const float4*)&xsT[kk][tm * 4];
            b0.f = *(const float4*)&ws[k][tn * 8];
            b1.f = *(const float4*)&ws[k][tn * 8 + 4];
            unsigned long long bv[4] = {b0.u[0], b0.u[1], b1.u[0], b1.u[1]};
            #pragma unroll
            for (int i = 0; i < 4; i++) {
                unsigned int au = __float_as_uint(av.s[i]);
                unsigned long long a2;
                asm("mov.b64 %0, {%1, %1};" : "=l"(a2) : "r"(au));
                #pragma unroll
                for (int j = 0; j < 4; j++)
                    asm("fma.rn.f32x2 %0, %1, %2, %0;"
                        : "+l"(acc2[i][j]) : "l"(a2), "l"(bv[j]));
            }
        }
    }

    float4* Y4 = (float4*)g_h;
    #pragma unroll
    for (int i = 0; i < 4; i++) {
        int m = row0 + tm * 4 + i;
        if (m < NN) {
            F4U64 o0, o1;
            o0.u[0] = acc2[i][0]; o0.u[1] = acc2[i][1];
            o1.u[0] = acc2[i][2]; o1.u[1] = acc2[i][3];
            Y4[(size_t)m * 32 + tn * 2]     = o0.f;
            Y4[(size_t)m * 32 + tn * 2 + 1] = o1.f;
        }
    }
}

__global__ void __launch_bounds__(256) k_gemm(const float* __restrict__ X,
                                              const float* __restrict__ W) {
    __shared__ __align__(16) float xsT[128][68];
    __shared__ __align__(16) float ws[16][128];
    int tid  = threadIdx.x;
    int row0 = blockIdx.x * 64;
    const float4* X4 = (const float4*)X;
    for (int t = tid; t < 64 * 32; t += 256) {
        int r = t >> 5, c4 = t & 31;
        float4 v = make_float4(0.f, 0.f, 0.f, 0.f);
        int m = row0 + r;
        if (m < NN) v = X4[(size_t)m * 32 + c4];
        int c = c4 * 4;
        xsT[c + 0][r] = v.x; xsT[c + 1][r] = v.y;
        xsT[c + 2][r] = v.z; xsT[c + 3][r] = v.w;
    }
    gemm_core(xsT, ws, W, row0, tid);
}

// ---------------- fused apply(prev layer) + GEMM(this layer) ----------------
// load stage: x_new = elu((h2 - am)*wr + b) + xres; write x_new to out AND smem.
__global__ void __launch_bounds__(256) k_applygemm(const float* __restrict__ xres,
                                                   const float* __restrict__ gnb,
                                                   const float* __restrict__ W,
                                                   float* __restrict__ out) {
    __shared__ __align__(16) float xsT[128][68];
    __shared__ __align__(16) float ws[16][128];
    int tid  = threadIdx.x;
    int row0 = blockIdx.x * 64;
    for (int t = tid; t < 64 * 32; t += 256) {
        int r = t >> 5, c4 = t & 31;
        float4 v = make_float4(0.f, 0.f, 0.f, 0.f);
        int m = row0 + r;
        if (m < NN) {
            int g = g_batch[m];
            float4 h = ((const float4*)g_h2)[(size_t)m * 32 + c4];
            float4 a = ((const float4*)g_am)[g * 32 + c4];
            float4 w = ((const float4*)g_wr)[g * 32 + c4];
            float4 b = ((const float4*)gnb)[c4];
            float4 x = ((const float4*)xres)[(size_t)m * 32 + c4];
            float z;
            z = (h.x - a.x) * w.x + b.x; v.x = (z > 0.f ? z : expm1f(z)) + x.x;
            z = (h.y - a.y) * w.y + b.y; v.y = (z > 0.f ? z : expm1f(z)) + x.y;
            z = (h.z - a.z) * w.z + b.z; v.z = (z > 0.f ? z : expm1f(z)) + x.z;
            z = (h.w - a.w) * w.w + b.w; v.w = (z > 0.f ? z : expm1f(z)) + x.w;
            ((float4*)out)[(size_t)m * 32 + c4] = v;
        }
        int c = c4 * 4;
        xsT[c + 0][r] = v.x; xsT[c + 1][r] = v.y;
        xsT[c + 2][r] = v.z; xsT[c + 3][r] = v.w;
    }
    gemm_core(xsT, ws, W, row0, tid);
}

// ---------------- SpMM: g_h2[d] = bias + selfw*h[d] + sum_e w[e]*h[col[e]] ----------------
__global__ void k_spmm(const float* __restrict__ bias) {
    int n    = (blockIdx.x * blockDim.x + threadIdx.x) >> 5;
    int lane = threadIdx.x & 31;
    if (n >= NN) return;
    const float4* h4 = (const float4*)g_h;
    float4 acc = ((const float4*)bias)[lane];
    float dn = g_dis[n];
    float sw = dn * dn;
    float4 hv = h4[(size_t)n * 32 + lane];
    acc.x = fmaf(sw, hv.x, acc.x);
    acc.y = fmaf(sw, hv.y, acc.y);
    acc.z = fmaf(sw, hv.z, acc.z);
    acc.w = fmaf(sw, hv.w, acc.w);
    int s = g_rowptr[n], e = g_rowptr[n + 1];
    int i = s;
    for (; i + 4 <= e; i += 4) {
        int2 e0 = g_edge[i],     e1 = g_edge[i + 1];
        int2 e2 = g_edge[i + 2], e3 = g_edge[i + 3];
        float w0 = __int_as_float(e0.y), w1 = __int_as_float(e1.y);
        float w2 = __int_as_float(e2.y), w3 = __int_as_float(e3.y);
        float4 v0 = h4[(size_t)e0.x * 32 + lane];
        float4 v1 = h4[(size_t)e1.x * 32 + lane];
        float4 v2 = h4[(size_t)e2.x * 32 + lane];
        float4 v3 = h4[(size_t)e3.x * 32 + lane];
        acc.x = fmaf(w0, v0.x, acc.x); acc.y = fmaf(w0, v0.y, acc.y);
        acc.z = fmaf(w0, v0.z, acc.z); acc.w = fmaf(w0, v0.w, acc.w);
        acc.x = fmaf(w1, v1.x, acc.x); acc.y = fmaf(w1, v1.y, acc.y);
        acc.z = fmaf(w1, v1.z, acc.z); acc.w = fmaf(w1, v1.w, acc.w);
        acc.x = fmaf(w2, v2.x, acc.x); acc.y = fmaf(w2, v2.y, acc.y);
        acc.z = fmaf(w2, v2.z, acc.z); acc.w = fmaf(w2, v2.w, acc.w);
        acc.x = fmaf(w3, v3.x, acc.x); acc.y = fmaf(w3, v3.y, acc.y);
        acc.z = fmaf(w3, v3.z, acc.z); acc.w = fmaf(w3, v3.w, acc.w);
    }
    for (; i < e; i++) {
        int2 e0 = g_edge[i];
        float w0 = __int_as_float(e0.y);
        float4 v0 = h4[(size_t)e0.x * 32 + lane];
        acc.x = fmaf(w0, v0.x, acc.x); acc.y = fmaf(w0, v0.y, acc.y);
        acc.z = fmaf(w0, v0.z, acc.z); acc.w = fmaf(w0, v0.w, acc.w);
    }
    ((float4*)g_h2)[(size_t)n * 32 + lane] = acc;
}

// ---------------- GraphNorm stats: one pass, grid (GG, 4 feature-chunks) ----------------
__global__ void __launch_bounds__(256) k_stats(const float* __restrict__ alpha,
                                               const float* __restrict__ gw) {
    int g = blockIdx.x;
    int fc = blockIdx.y;
    int t = threadIdx.x;
    int f = fc * 32 + (t & 31), sl = t >> 5;
    int s = g_gptr[g], e = g_gptr[g + 1];
    int cnt = e - s;
    __shared__ float ssum[8][32], ssq[8][32];
    float sum = 0.f, sq = 0.f;
    const float* p = g_h2 + (size_t)s * DD + f;
    #pragma unroll 4
    for (int n = sl; n < cnt; n += 8) {
        float v = p[(size_t)n * DD];
        sum += v; sq = fmaf(v, v, sq);
    }
    ssum[sl][t & 31] = sum; ssq[sl][t & 31] = sq;
    __syncthreads();
    if (t < 32) {
        if (cnt <= 0) { g_am[g * DD + f] = 0.f; g_wr[g * DD + f] = 0.f; return; }
        float S = 0.f, Q = 0.f;
        #pragma unroll
        for (int i = 0; i < 8; i++) { S += ssum[i][t]; Q += ssq[i][t]; }
        float inv = 1.f / (float)cnt;
        float mean = S * inv;
        float am = alpha[f] * mean;
        float var = fmaf(am, am, fmaf(-2.f * am, mean, Q * inv));
        g_am[g * DD + f] = am;
        g_wr[g * DD + f] = gw[f] * rsqrtf(var + EPSV);
    }
}

// ---------------- normalize + ELU + residual -> out (final layer only) ----------------
__global__ void k_apply(const float* __restrict__ xres, const float* __restrict__ gnb,
                        float* __restrict__ out) {
    int t = blockIdx.x * blockDim.x + threadIdx.x;
    if (t >= NN * 32) return;
    int n = t >> 5, q = t & 31;
    int g = g_batch[n];
    float4 h = ((const float4*)g_h2)[t];
    float4 a = ((const float4*)g_am)[g * 32 + q];
    float4 w = ((const float4*)g_wr)[g * 32 + q];
    float4 b = ((const float4*)gnb)[q];
    float4 r = ((const float4*)xres)[t];
    float4 o;
    float v;
    v = (h.x - a.x) * w.x + b.x; o.x = (v > 0.f ? v : expm1f(v)) + r.x;
    v = (h.y - a.y) * w.y + b.y; o.y = (v > 0.f ? v : expm1f(v)) + r.y;
    v = (h.z - a.z) * w.z + b.z; o.z = (v > 0.f ? v : expm1f(v)) + r.z;
    v = (h.w - a.w) * w.w + b.w; o.w = (v > 0.f ? v : expm1f(v)) + r.w;
    ((float4*)out)[t] = o;
}

// ---------------- global add pool: grid (GG, 4 chunks) x 256 ----------------
__global__ void __launch_bounds__(256) k_pool(const float* __restrict__ x) {
    int g = blockIdx.x;
    int fc = blockIdx.y;
    int t = threadIdx.x;
    int f = fc * 32 + (t & 31), sl = t >> 5;
    int s = g_gptr[g], e = g_gptr[g + 1];
    int cnt = e - s;
    __shared__ float ssum[8][32];
    float sum = 0.f;
    const float* p = x + (size_t)s * DD + f;
    #pragma unroll 4
    for (int n = sl; n < cnt; n += 8) sum += p[(size_t)n * DD];
    ssum[sl][t & 31] = sum;
    __syncthreads();
    if (t < 32) {
        float S = 0.f;
        #pragma unroll
        for (int i = 0; i < 8; i++) S += ssum[i][t];
        g_pool[g * DD + f] = S;
    }
}

// ---------------- MLP head (reads g_pool) ----------------
__global__ void k_mlp(const float* __restrict__ w1, const float* __restrict__ b1,
                      const float* __restrict__ bng, const float* __restrict__ bnb,
                      const float* __restrict__ bnm, const float* __restrict__ bnv,
                      const float* __restrict__ w2, const float* __restrict__ b2,
                      float* __restrict__ out) {
    int g = blockIdx.x, d = threadIdx.x;
    __shared__ float p[DD], z1[DD];
    p[d] = g_pool[g * DD + d];
    __syncthreads();
    float z = b1[d];
    #pragma unroll 4
    for (int k = 0; k < DD; k++) z = fmaf(p[k], w1[k * DD + d], z);
    z = bng[d] * (z - bnm[d]) * rsqrtf(bnv[d] + EPSV) + bnb[d];
    z = z > 0.f ? z : 0.f;
    z1[d] = z;
    __syncthreads();
    if (d < NCLS) {
        float o = b2[d];
        #pragma unroll 4
        for (int k = 0; k < DD; k++) o = fmaf(z1[k], w2[k * NCLS + d], o);
        out[(size_t)NN * DD + g * NCLS + d] = o;
    }
}

// ---------------- launch ----------------
extern "C" void kernel_launch(void* const* d_in, const int* in_sizes, int n_in,
                              void* d_out, int out_size) {
    const float* x0     = (const float*)d_in[0];
    const void*  ei     = d_in[1];
    const void*  batch  = d_in[2];
    const float* conv_w = (const float*)d_in[3];
    const float* conv_b = (const float*)d_in[4];
    const float* gn_w   = (const float*)d_in[5];
    const float* gn_b   = (const float*)d_in[6];
    const float* gn_ms  = (const float*)d_in[7];
    const float* w1     = (const float*)d_in[8];
    const float* b1     = (const float*)d_in[9];
    const float* bng    = (const float*)d_in[10];
    const float* bnb    = (const float*)d_in[11];
    const float* bnm    = (const float*)d_in[12];
    const float* bnv    = (const float*)d_in[13];
    const float* w2     = (const float*)d_in[14];
    const float* b2     = (const float*)d_in[15];
    float* out = (float*)d_out;

    // layer-0 GEMM depends only on x0/conv_w -> launch 4th so ncu profiles it.
    k_detect<<<1, 256>>>((const int*)ei);
    k_init<<<256, 256>>>();
    k_hist<<<(EE + 255) / 256, 256>>>(ei);
    k_gemm<<<(NN + 63) / 64, 256>>>(x0, conv_w);
    k_cvt_batch<<<(NN + 255) / 256, 256>>>(batch);
    k_scan1<<<NB, 256>>>();
    k_scan2<<<1, 32>>>();
    k_scan3<<<NB, 256>>>();
    k_scatter<<<(EE + 255) / 256, 256>>>(ei);

    // layer 0 aggregate + stats
    k_spmm<<<(NN + 7) / 8, 256>>>(conv_b);
    k_stats<<<dim3(GG, 4), 256>>>(gn_ms, gn_w);

    // layers 1..3: fused apply(l-1) + gemm(l), then spmm + stats
    const float* xres = x0;
    for (int l = 1; l < LL; l++) {
        k_applygemm<<<(NN + 63) / 64, 256>>>(xres, gn_b + (size_t)(l - 1) * DD,
                                             conv_w + (size_t)l * DD * DD, out);
        xres = out;
        k_spmm<<<(NN + 7) / 8, 256>>>(conv_b + (size_t)l * DD);
        k_stats<<<dim3(GG, 4), 256>>>(gn_ms + (size_t)l * DD, gn_w + (size_t)l * DD);
    }

    // final apply (layer 3) + head
    k_apply<<<(NN * 32 + 255) / 256, 256>>>(xres, gn_b + (size_t)(LL - 1) * DD, out);
    k_pool<<<dim3(GG, 4), 256>>>(out);
    k_mlp<<<GG, DD>>>(w1, b1, bng, bnb, bnm, bnv, w2, b2, out);
}